// round 9
// baseline (speedup 1.0000x reference)
#include <cuda_runtime.h>
#include <math.h>

// Fixed problem shape: NQ=2048, NT=131072, D=64, E=2,000,000, M=1024
#define NQ_C 2048
#define NT_C 131072
#define E_C  2000000
#define NSCAN 128        // scan blocks (1024 elems each)

#define FULLM 0xffffffffu

#define SZ_BLOCKS 2048   // fused scatter+za blocks (256 thr: warps 0-3 za, 4-7 scatter)

// ---------------- scratch (static device globals; no allocation) ----------------
__device__ float  g_zab[(size_t)NT_C * 128];  // row v: [2d]=za[d]=Wa@xt, [2d+1]=zb[d]=Wb@xt
__device__ int    g_degv[NT_C];               // zeroed at start; re-zeroed by main_kernel
__device__ int    g_offv[NT_C + 1];
__device__ int    g_curv[NT_C];
__device__ int    g_usort[E_C];               // u per edge, grouped by v
__device__ unsigned long long g_pub[NSCAN];   // lookback publish: (flag<<32)|aggregate

// ---------------- packed f32x2 helpers ----------------
__device__ __forceinline__ unsigned long long pk2(float a, float b) {
    unsigned long long r;
    asm("mov.b64 %0, {%1, %2};" : "=l"(r) : "f"(a), "f"(b));
    return r;
}
__device__ __forceinline__ void fma2(unsigned long long& d,
                                     unsigned long long a, unsigned long long b) {
    asm("fma.rn.f32x2 %0, %1, %2, %0;" : "+l"(d) : "l"(a), "l"(b));
}
__device__ __forceinline__ float2 upk2(unsigned long long v) {
    float lo, hi;
    asm("mov.b64 {%0, %1}, %2;" : "=f"(lo), "=f"(hi) : "l"(v));
    return make_float2(lo, hi);
}

// ---------------- count ----------------
__global__ void count_kernel(const int* __restrict__ v_idx, int E) {
    int stride = gridDim.x * blockDim.x;
    for (int i = blockIdx.x * blockDim.x + threadIdx.x; i < E; i += stride)
        atomicAdd(&g_degv[v_idx[i]], 1);   // no return -> REDG
}

// ---------------- single-kernel scan with parallel lookback ----------------
__global__ __launch_bounds__(1024) void scan_kernel(int NT, int E) {
    __shared__ int wsum[32];
    __shared__ int red[32];
    int tid = threadIdx.x, lane = tid & 31, wid = tid >> 5;
    int b = blockIdx.x;
    int i = b * 1024 + tid;
    int v = (i < NT) ? g_degv[i] : 0;
    int x = v;
#pragma unroll
    for (int d = 1; d < 32; d <<= 1) {
        int y = __shfl_up_sync(FULLM, x, d);
        if (lane >= d) x += y;
    }
    if (lane == 31) wsum[wid] = x;
    __syncthreads();
    if (wid == 0) {
        int w = wsum[lane];
#pragma unroll
        for (int d = 1; d < 32; d <<= 1) {
            int y = __shfl_up_sync(FULLM, w, d);
            if (lane >= d) w += y;
        }
        wsum[lane] = w;
    }
    __syncthreads();
    int excl = x - v + (wid ? wsum[wid - 1] : 0);
    int total = wsum[31];

    if (tid == 0)
        atomicExch(&g_pub[b], (1ULL << 32) | (unsigned int)total);

    int myval = 0;
    if (tid < b) {
        unsigned long long p;
        do { p = atomicAdd(&g_pub[tid], 0ULL); } while ((p >> 32) == 0);
        myval = (int)(p & 0xffffffffu);
    }
    int r = myval;
#pragma unroll
    for (int d = 16; d > 0; d >>= 1) r += __shfl_xor_sync(FULLM, r, d);
    if (lane == 0) red[wid] = r;
    __syncthreads();
    if (wid == 0) {
        int t = (lane < 32) ? red[lane] : 0;
#pragma unroll
        for (int d = 16; d > 0; d >>= 1) t += __shfl_xor_sync(FULLM, t, d);
        if (lane == 0) red[0] = t;
    }
    __syncthreads();
    int offset = red[0];

    if (i < NT) {
        int o = excl + offset;
        g_offv[i] = o;
        g_curv[i] = o;
    }
    if (b == gridDim.x - 1 && tid == 0) g_offv[NT] = E;
}

// ---------------- fused scatter + za (independent work, shared SMs) ----------------
// warps 0-3: Z = (Wa@xt, Wb@xt) per target (f32x2 FMA, smem-packed W + dup-x pairs)
// warps 4-7: counting-sort scatter of u by v
__global__ __launch_bounds__(256) void scatza_kernel(
    const float* __restrict__ Xt,
    const int* __restrict__ u_idx, const int* __restrict__ v_idx,
    const float* __restrict__ Wa, const float* __restrict__ Wb, int E, int NT)
{
    __shared__ __align__(16) float sWf[64 * 32 * 4];   // 32 KB packed W
    __shared__ unsigned long long sXp[4][4][64];       // 8 KB duplicated (x,x) pairs

    int tid = threadIdx.x;

    // all threads: build packed W in smem (coalesced float4 loads, scattered STS)
    for (int j = tid; j < 64 * 16; j += 256) {
        int r = j >> 4, c4 = (j & 15) << 2;
        int l = r >> 1, half = r & 1;
        float4 wa = reinterpret_cast<const float4*>(Wa)[j];
        float4 wb = reinterpret_cast<const float4*>(Wb)[j];
#pragma unroll
        for (int k = 0; k < 4; ++k) {
            int f = c4 + k;
            float va = (k == 0 ? wa.x : k == 1 ? wa.y : k == 2 ? wa.z : wa.w);
            float vb = (k == 0 ? wb.x : k == 1 ? wb.y : k == 2 ? wb.z : wb.w);
            sWf[(f * 32 + l) * 4 + half]     = va;
            sWf[(f * 32 + l) * 4 + 2 + half] = vb;
        }
    }
    __syncthreads();   // all 256 threads participate

    int lane = tid & 31, warp = tid >> 5;

    if (warp >= 4) {
        // ---- scatter part ----
        int gtid = blockIdx.x * 128 + (tid - 128);
        int stride = SZ_BLOCKS * 128;
        for (int i = gtid; i < E; i += stride) {
            int vv = v_idx[i];
            int slot = atomicAdd(&g_curv[vv], 1);
            g_usort[slot] = u_idx[i];
        }
        return;
    }

    // ---- za part ----
    const ulonglong2* sW = reinterpret_cast<const ulonglong2*>(sWf);
    int gwid = blockIdx.x * 4 + warp;
    int nW = SZ_BLOCKS * 4;
    int nGrp = NT >> 2;

    for (int grp = gwid; grp < nGrp; grp += nW) {
        int r0 = grp * 4;
#pragma unroll
        for (int r = 0; r < 4; ++r) {
            float2 x = reinterpret_cast<const float2*>(Xt + (size_t)(r0 + r) * 64)[lane];
            sXp[warp][r][2 * lane]     = pk2(x.x, x.x);
            sXp[warp][r][2 * lane + 1] = pk2(x.y, x.y);
        }
        __syncwarp();

        unsigned long long az0 = 0, bz0 = 0, az1 = 0, bz1 = 0;
        unsigned long long az2 = 0, bz2 = 0, az3 = 0, bz3 = 0;
#pragma unroll
        for (int f = 0; f < 64; ++f) {
            ulonglong2 w2 = sW[f * 32 + lane];
            unsigned long long p0 = sXp[warp][0][f];
            unsigned long long p1 = sXp[warp][1][f];
            unsigned long long p2 = sXp[warp][2][f];
            unsigned long long p3 = sXp[warp][3][f];
            fma2(az0, w2.x, p0); fma2(bz0, w2.y, p0);
            fma2(az1, w2.x, p1); fma2(bz1, w2.y, p1);
            fma2(az2, w2.x, p2); fma2(bz2, w2.y, p2);
            fma2(az3, w2.x, p3); fma2(bz3, w2.y, p3);
        }
#pragma unroll
        for (int r = 0; r < 4; ++r) {
            float2 az = upk2(r == 0 ? az0 : r == 1 ? az1 : r == 2 ? az2 : az3);
            float2 bz = upk2(r == 0 ? bz0 : r == 1 ? bz1 : r == 2 ? bz2 : bz3);
            reinterpret_cast<float4*>(g_zab + (size_t)(r0 + r) * 128)[lane] =
                make_float4(az.x, bz.x, az.y, bz.y);
        }
        __syncwarp();
    }
}

// ---------------- main: warp/target, max-free, shfl-free activations+aggregation ----
// 4-edge groups: lane (sub,g) scores edge 4t+sub on dims 8g..8g+7; after the
// 3-level xor-reduce all 8 lanes of the sub-group hold the edge's full score, so
// activation + weight + aggregation are lane-local (no routing/agg shuffles).
// s/swb are accumulated 8x per edge (once per g-lane); fixed by 8/s at the end.
__global__ __launch_bounds__(256, 5) void main_kernel(
    const float* __restrict__ Xq, const float* __restrict__ Xt,
    const float* __restrict__ ba, const float* __restrict__ bb,
    const int* __restrict__ uc,
    float* __restrict__ outXt, int NT, int NTM)
{
    int warpId = threadIdx.x >> 5;
    int lane   = threadIdx.x & 31;
    int v = blockIdx.x * 8 + warpId;
    if (v >= NT) return;

    // reset replay scratch (deterministic per-call state)
    if (lane == 0) {
        g_degv[v] = 0;
        if (v < NSCAN) g_pub[v] = 0ULL;
    }

    // consensus rows: v in [NT-M, NT) -> Xq[uc[v-(NT-M)]], no incoming edges
    if (v >= NTM) {
        int u = __ldg(uc + (v - NTM));
        float2 q = reinterpret_cast<const float2*>(Xq + (size_t)u * 64)[lane];
        reinterpret_cast<float2*>(outXt + (size_t)v * 64)[lane] = q;
        return;
    }

    int o   = g_offv[v];
    int deg = g_offv[v + 1] - o;
    if (deg == 0) {
        float2 xt2 = reinterpret_cast<const float2*>(Xt + (size_t)v * 64)[lane];
        reinterpret_cast<float2*>(outXt + (size_t)v * 64)[lane] = xt2;
        return;
    }

    int g = lane & 7, sub = lane >> 3;
    const float4* zr = reinterpret_cast<const float4*>(g_zab + (size_t)v * 128);
    float4 z0 = zr[4 * g + 0], z1 = zr[4 * g + 1];
    float4 z2 = zr[4 * g + 2], z3 = zr[4 * g + 3];
    float bav = __ldg(ba), bbv = __ldg(bb);

    float s = 0.f, swb = 0.f;
    float acc[8];
#pragma unroll
    for (int d = 0; d < 8; ++d) acc[d] = 0.f;

    int nch = (deg + 15) >> 4;
    for (int c = 0; c < nch; ++c) {
        int start = o + c * 16;
        int cnt = deg - c * 16; if (cnt > 16) cnt = 16;

        int el = lane & 15;
        int li = (el < cnt) ? el : (cnt - 1);
        int u_l = g_usort[start + li];

        int ng = (cnt + 3) >> 2;   // 4-edge groups in this chunk
#pragma unroll 4
        for (int t = 0; t < ng; ++t) {
            int e = 4 * t + sub;                     // this sub-group's edge
            int ec = (e < cnt) ? e : (cnt - 1);
            int ue = __shfl_sync(FULLM, u_l, ec);
            const float4* qr = reinterpret_cast<const float4*>(Xq + (size_t)ue * 64);
            float4 q0 = qr[2 * g], q1 = qr[2 * g + 1];

            float pa = q0.x * z0.x + q0.y * z0.z + q0.z * z1.x + q0.w * z1.z
                     + q1.x * z2.x + q1.y * z2.z + q1.z * z3.x + q1.w * z3.z;
            float pb = q0.x * z0.y + q0.y * z0.w + q0.z * z1.y + q0.w * z1.w
                     + q1.x * z2.y + q1.y * z2.w + q1.z * z3.y + q1.w * z3.w;
#pragma unroll
            for (int sh = 4; sh > 0; sh >>= 1) {
                pa += __shfl_xor_sync(FULLM, pa, sh);
                pb += __shfl_xor_sync(FULLM, pb, sh);
            }
            // every lane of the sub-group now holds edge e's full scores
            float da = pa + bav, db = pb + bbv;
            float alpha = (da > 0.f) ? da : (__expf(da) - 1.0f);
            float beta  = 1.0f / (1.0f + __expf(-db));
            float w_ = (e < cnt) ? __expf(alpha) : 0.f;
            s += w_;                      // 8x-counted (once per g-lane)
            float wb = w_ * beta;
            swb += wb;
            float cb = w_ - wb;           // w * (1 - beta)

            acc[0] = fmaf(cb, q0.x, acc[0]);
            acc[1] = fmaf(cb, q0.y, acc[1]);
            acc[2] = fmaf(cb, q0.z, acc[2]);
            acc[3] = fmaf(cb, q0.w, acc[3]);
            acc[4] = fmaf(cb, q1.x, acc[4]);
            acc[5] = fmaf(cb, q1.y, acc[5]);
            acc[6] = fmaf(cb, q1.z, acc[6]);
            acc[7] = fmaf(cb, q1.w, acc[7]);
        }
    }

    // s/swb: full warp reduce (gives 8x the true sums; ratio unaffected)
#pragma unroll
    for (int sh = 16; sh > 0; sh >>= 1) {
        s   += __shfl_xor_sync(FULLM, s, sh);
        swb += __shfl_xor_sync(FULLM, swb, sh);
    }
    // acc: reduce across the 4 sub groups (same g)
#pragma unroll
    for (int d = 0; d < 8; ++d) {
        acc[d] += __shfl_xor_sync(FULLM, acc[d], 8);
        acc[d] += __shfl_xor_sync(FULLM, acc[d], 16);
    }

    float inv = 8.f / s;       // 1 / trueS
    float k = swb / s;         // trueSwb / trueS
    if (sub == 0) {   // lanes 0..7: lane g writes dims 8g..8g+7
        const float4* xr = reinterpret_cast<const float4*>(Xt + (size_t)v * 64);
        float4 xa = xr[2 * g], xb = xr[2 * g + 1];
        float4 o0 = make_float4(fmaf(k, xa.x, acc[0] * inv), fmaf(k, xa.y, acc[1] * inv),
                                fmaf(k, xa.z, acc[2] * inv), fmaf(k, xa.w, acc[3] * inv));
        float4 o1 = make_float4(fmaf(k, xb.x, acc[4] * inv), fmaf(k, xb.y, acc[5] * inv),
                                fmaf(k, xb.z, acc[6] * inv), fmaf(k, xb.w, acc[7] * inv));
        float4* orow = reinterpret_cast<float4*>(outXt + (size_t)v * 64);
        orow[2 * g]     = o0;
        orow[2 * g + 1] = o1;
    }
}

// ---------------- launcher ----------------
extern "C" void kernel_launch(void* const* d_in, const int* in_sizes, int n_in,
                              void* d_out, int out_size) {
    const float* Xq = (const float*)d_in[0];
    const float* Xt = (const float*)d_in[1];
    const float* Wa = (const float*)d_in[2];
    const float* ba = (const float*)d_in[3];
    const float* Wb = (const float*)d_in[4];
    const float* bb = (const float*)d_in[5];
    const int* u_idx = (const int*)d_in[6];
    const int* v_idx = (const int*)d_in[7];
    const int* uc = (const int*)d_in[8];

    int NQ = in_sizes[0] / 64;
    int NT = in_sizes[1] / 64;
    int E  = in_sizes[6];
    int M  = in_sizes[8];

    float* out = (float*)d_out;
    float* outXt = out + (size_t)NQ * 64;

    count_kernel<<<2048, 256>>>(v_idx, E);                                          // idx 0
    scan_kernel<<<NSCAN, 1024>>>(NT, E);                                            // idx 1
    scatza_kernel<<<SZ_BLOCKS, 256>>>(Xt, u_idx, v_idx, Wa, Wb, E, NT);             // idx 2
    main_kernel<<<(NT + 7) / 8, 256>>>(Xq, Xt, ba, bb, uc, outXt, NT, NT - M);      // idx 3 (profiled)

    cudaMemcpyAsync(out, Xq, (size_t)NQ * 64 * sizeof(float),
                    cudaMemcpyDeviceToDevice, 0);
}